// round 15
// baseline (speedup 1.0000x reference)
#include <cuda_runtime.h>
#include <cuda_pipeline.h>
#include <math.h>
#include <stdint.h>

#define NTOK 16384
#define DDIM 2048
#define NEXP 64
#define TM   128
#define NBLK (NTOK / TM)      // 128 blocks
#define NTHR 1024             // 32 warps, 8 per SMSP
#define KC   64
#define NCHUNK (DDIM / KC)    // 32 chunks
#define APIT  36              // packed-A pitch in u64 (pairs): conflict-free LDS.64
#define ASZ64 (TM * APIT)     // 4608 u64 per buffer
#define BPITCH 72             // packed-B pitch (u32): conflict-free scalar LDS
#define BSZ (32 * BPITCH)     // 2304 u32 per buffer per array
#define NOISE_STD (1.0f / 64.0f)

// smem byte offsets: A double-buffered, B TRIPLE-buffered (stage target is
// never a buffer still being read in the current iteration)
#define OFF_AP 0                          // u64 Ap[2][4608]  = 73728 B
#define OFF_BH 73728                      // u32 Bh[3][2304]  = 27648 B
#define OFF_BL (OFF_BH + 27648)           // u32 Bl[3][2304]  = 27648 B
#define SMEM_BYTES (OFF_BL + 27648)       // 129024 B -> 1 CTA/SM

// device scratch (no cudaMalloc allowed)
__device__ float    g_part_imp[NBLK][NEXP];
__device__ float    g_part_p[NBLK][NEXP];
// packed W bf16x2: g_wbh[k2*64+n] = {lo: bf16(W[2k2][n]), hi: bf16(W[2k2+1][n])}
__device__ uint32_t g_wbh[(DDIM / 2) * NEXP];
__device__ uint32_t g_wbl[(DDIM / 2) * NEXP];
__device__ int      g_ctr;

// pack two fp32 -> bf16x2 (RN): lower half = e0, upper half = e1
__device__ __forceinline__ uint32_t pack_bf16x2(float e0, float e1) {
    uint32_t r;
    asm("cvt.rn.satfinite.bf16x2.f32 %0, %1, %2;" : "=r"(r) : "f"(e1), "f"(e0));
    return r;
}
__device__ __forceinline__ void mma_bf16(float* c, const uint32_t* a,
                                         uint32_t b0, uint32_t b1) {
    asm volatile(
        "mma.sync.aligned.m16n8k16.row.col.f32.bf16.bf16.f32 "
        "{%0,%1,%2,%3}, {%4,%5,%6,%7}, {%8,%9}, {%0,%1,%2,%3};"
        : "+f"(c[0]), "+f"(c[1]), "+f"(c[2]), "+f"(c[3])
        : "r"(a[0]), "r"(a[1]), "r"(a[2]), "r"(a[3]), "r"(b0), "r"(b1));
}
// split a float2 (consecutive k) into bf16x2 hi and lo parts
__device__ __forceinline__ void split_pair(float2 p, uint32_t& hi2, uint32_t& lo2) {
    hi2 = pack_bf16x2(p.x, p.y);
    const float h0 = __uint_as_float(hi2 << 16);
    const float h1 = __uint_as_float(hi2 & 0xFFFF0000u);
    lo2 = pack_bf16x2(p.x - h0, p.y - h1);
}
__device__ __forceinline__ bool gtv(float a, int ia, float b, int ib) {
    return (a > b) || (a == b && ia < ib);
}

// ---- prologue: split W into packed bf16x2 hi/lo pairs (k-pairs in one u32)
__global__ void __launch_bounds__(256) wconv(const float* __restrict__ W) {
    const int idx = blockIdx.x * 256 + threadIdx.x;   // 256 blocks -> 65536
    const int k2 = idx >> 6, n = idx & 63;
    const float f0 = W[(size_t)(2 * k2) * NEXP + n];
    const float f1 = W[(size_t)(2 * k2 + 1) * NEXP + n];
    uint32_t h2, l2;
    split_pair(make_float2(f0, f1), h2, l2);
    g_wbh[k2 * 64 + n] = h2;
    g_wbl[k2 * 64 + n] = l2;
}

__global__ void __launch_bounds__(NTHR)
router_main(const float* __restrict__ x, const float* __restrict__ bias_g,
            const float* __restrict__ noise, float* __restrict__ out) {
    extern __shared__ __align__(16) char smraw[];
    float* sm = (float*)smraw;
    uint2* Ap_base = (uint2*)(smraw + OFF_AP);
    uint32_t* Bh_base = (uint32_t*)(smraw + OFF_BH);
    uint32_t* Bl_base = (uint32_t*)(smraw + OFF_BL);

    const int tid  = threadIdx.x;
    const int lane = tid & 31;
    const int w    = tid >> 5;    // warp 0..31
    const int mg   = w & 7;       // m-tile: rows [mg*16, mg*16+16)
    const int ng   = w >> 3;      // n-group 0..3: cols [ng*16, ng*16+16)
    const int g    = lane >> 2;   // 0..7
    const int l4   = lane & 3;    // 0..3
    const int bm   = blockIdx.x * TM;

    // A staging: 8 threads per token row, 8 floats (4 k-pairs) each
    const int tokS = tid >> 3;         // 0..127
    const int pS   = (tid & 7) * 4;    // pair base 0..28
    const float* xsrc = x + (size_t)(bm + tokS) * DDIM + pS * 2;
    // B staging: thread copies 2 u32 of packed row kB2 (both hi and lo arrays)
    const int kB2 = tid >> 5;          // 0..31
    const int qB  = lane * 2;          // 0..62

    float4 xa, xb;                      // raw A prefetch registers
    auto ldgA = [&](int c) {
        if (c < NCHUNK) {
            const float4* p = (const float4*)(xsrc + c * KC);
            xa = p[0];
            xb = p[1];
        }
    };
    auto convSTS = [&](int c) {
        if (c < NCHUNK) {
            uint32_t h0, l0, h1, l1, h2, l2, h3, l3;
            split_pair(make_float2(xa.x, xa.y), h0, l0);
            split_pair(make_float2(xa.z, xa.w), h1, l1);
            split_pair(make_float2(xb.x, xb.y), h2, l2);
            split_pair(make_float2(xb.z, xb.w), h3, l3);
            uint4* dst = (uint4*)(Ap_base + (c & 1) * ASZ64 + tokS * APIT + pS);
            dst[0] = make_uint4(h0, l0, h1, l1);
            dst[1] = make_uint4(h2, l2, h3, l3);
        }
    };
    auto stageB = [&](int c) {
        if (c < NCHUNK) {
            const int bsrc = c * (KC / 2) * 64 + kB2 * 64 + qB;
            const int bdst = (c % 3) * BSZ + kB2 * BPITCH + qB;
            __pipeline_memcpy_async(Bh_base + bdst, g_wbh + bsrc, 8);
            __pipeline_memcpy_async(Bl_base + bdst, g_wbl + bsrc, 8);
        }
        __pipeline_commit();
    };

    float acc[2][4];
#pragma unroll
    for (int ni = 0; ni < 2; ni++)
#pragma unroll
        for (int r = 0; r < 4; r++) acc[ni][r] = 0.f;

    ldgA(0);
    stageB(0); stageB(1);
    convSTS(0);
    ldgA(1);
    __pipeline_wait_prior(1);   // B chunk 0 landed (thread-local)
    __syncthreads();            // packed A0 + B0 visible block-wide

    const int r0 = mg * 16 + g;

    for (int c = 0; c < NCHUNK; ++c) {
        // invariant: A(c)+B(c) visible block-wide; B(c+1) landed thread-locally
        //            (published by this iteration's end sync); xa/xb = raw c+1
        convSTS(c + 1);          // A buf ((c+1)&1): readers were iter c-1, synced
        ldgA(c + 2);             // prefetch raw A for next convert

        const uint2* Apu = Ap_base + (c & 1) * ASZ64;
        const uint32_t* Bh = Bh_base + (c % 3) * BSZ;
        const uint32_t* Bl = Bl_base + (c % 3) * BSZ;

#pragma unroll
        for (int ks = 0; ks < KC / 16; ks++) {      // 4 k16 steps
            const int pb = ks * 8 + l4;             // pair index (k0), +4 = k0+8
            const uint2 q00 = Apu[r0 * APIT + pb];
            const uint2 q10 = Apu[(r0 + 8) * APIT + pb];
            const uint2 q01 = Apu[r0 * APIT + pb + 4];
            const uint2 q11 = Apu[(r0 + 8) * APIT + pb + 4];
            const uint32_t ah[4] = {q00.x, q10.x, q01.x, q11.x};
            const uint32_t al[4] = {q00.y, q10.y, q01.y, q11.y};
#pragma unroll
            for (int ni = 0; ni < 2; ni++) {
                const int n = ng * 16 + ni * 8 + g;
                const uint32_t bh0 = Bh[pb * BPITCH + n];
                const uint32_t bh1 = Bh[(pb + 4) * BPITCH + n];
                const uint32_t bl0 = Bl[pb * BPITCH + n];
                const uint32_t bl1 = Bl[(pb + 4) * BPITCH + n];
                mma_bf16(acc[ni], ah, bh0, bh1);   // hh
                mma_bf16(acc[ni], ah, bl0, bl1);   // hl
                mma_bf16(acc[ni], al, bh0, bh1);   // lh
            }
        }

        stageB(c + 2);             // B buf ((c+2)%3): not read this iter or next;
                                   // its last readers (iter c-1) are behind a sync
        __pipeline_wait_prior(1);  // B chunk c+1 landed (thread-local)
        __syncthreads();           // publish A(c+1) STS + B(c+1) cp.async
    }

    // ---- store C into Ls[128][66] (reuses Ap region; loop ended with sync)
    float* Ls = sm;
#pragma unroll
    for (int ni = 0; ni < 2; ni++) {
        const int row = mg * 16 + g;
        const int col = ng * 16 + ni * 8 + l4 * 2;
        *(float2*)(Ls + row * 66 + col) = make_float2(acc[ni][0], acc[ni][1]);
        *(float2*)(Ls + (row + 8) * 66 + col) = make_float2(acc[ni][2], acc[ni][3]);
    }
    __syncthreads();

    // ---- per-token epilogue: warp w handles tokens [w*4, w*4+4)
    const int e0 = 2 * lane;
    const int e1 = 2 * lane + 1;
    const float bb0 = __ldg(bias_g + e0);
    const float bb1 = __ldg(bias_g + e1);

    float imp0 = 0.f, imp1 = 0.f, pa0 = 0.f, pa1 = 0.f;

    for (int tt = 0; tt < 4; ++tt) {
        const int tl = w * 4 + tt;
        const int t  = bm + tl;
        const float2 L2 = *(const float2*)(Ls + tl * 66 + e0);
        const float l0 = L2.x + bb0, l1 = L2.y + bb1;

        float mx = fmaxf(l0, l1);
#pragma unroll
        for (int off = 16; off; off >>= 1)
            mx = fmaxf(mx, __shfl_xor_sync(0xffffffffu, mx, off));
        const float s0 = __expf(l0 - mx);
        const float s1 = __expf(l1 - mx);
        float ss = s0 + s1;
#pragma unroll
        for (int off = 16; off; off >>= 1)
            ss += __shfl_xor_sync(0xffffffffu, ss, off);
        const float rs = 1.0f / ss;
        imp0 += s0 * rs;
        imp1 += s1 * rs;

        const float2 nz = *(const float2*)(noise + (size_t)t * NEXP + e0);
        const float n0 = fmaf(NOISE_STD, nz.x, l0);
        const float n1 = fmaf(NOISE_STD, nz.y, l1);
        float v1, v2;
        int i1, i2;
        if (n0 >= n1) { v1 = n0; i1 = e0; v2 = n1; i2 = e1; }
        else          { v1 = n1; i1 = e1; v2 = n0; i2 = e0; }
#pragma unroll
        for (int off = 16; off; off >>= 1) {
            const float ov1 = __shfl_xor_sync(0xffffffffu, v1, off);
            const int   oi1 = __shfl_xor_sync(0xffffffffu, i1, off);
            const float ov2 = __shfl_xor_sync(0xffffffffu, v2, off);
            const int   oi2 = __shfl_xor_sync(0xffffffffu, i2, off);
            if (gtv(ov1, oi1, v1, i1)) {
                if (gtv(v1, i1, ov2, oi2)) { v2 = v1; i2 = i1; }
                else                       { v2 = ov2; i2 = oi2; }
                v1 = ov1; i1 = oi1;
            } else if (gtv(ov1, oi1, v2, i2)) {
                v2 = ov1; i2 = oi1;
            }
        }

        const float ee = __expf(v2 - v1);
        const float g1 = 1.0f / (1.0f + ee);
        const float g2 = ee * g1;

        const float z0 = (v2 - l0) * 64.0f;
        const float z1 = (v2 - l1) * 64.0f;
        pa0 += normcdff(-z0);
        pa1 += normcdff(-z1);

        if (lane == 0) {
            out[2 * t + 0] = g1;
            out[2 * t + 1] = g2;
            out[2 * NTOK + 2 * t + 0] = (float)i1;
            out[2 * NTOK + 2 * t + 1] = (float)i2;
        }
    }

    // ---- block partials (deterministic layout; 32 warps)
    float* redI = sm + 8448;          // [32][64]
    float* redP = sm + 8448 + 2048;   // [32][64]
    redI[w * 64 + e0] = imp0;
    redI[w * 64 + e1] = imp1;
    redP[w * 64 + e0] = pa0;
    redP[w * 64 + e1] = pa1;
    __syncthreads();
    if (tid < NEXP) {
        float si = 0.f, sp = 0.f;
#pragma unroll
        for (int r = 0; r < 32; r++) {
            si += redI[r * 64 + tid];
            sp += redP[r * 64 + tid];
        }
        g_part_imp[blockIdx.x][tid] = si;
        g_part_p[blockIdx.x][tid]   = sp;
    }

    // ---- last CTA computes aux loss (fixed-order sums -> deterministic)
    __threadfence();
    __shared__ int s_ticket;
    if (tid == 0) s_ticket = atomicAdd(&g_ctr, 1);
    __syncthreads();
    if (s_ticket == NBLK - 1) {
        const int e = tid & 63;
        const int h = tid >> 6;  // 0..15
        float si = 0.f, sp = 0.f;
        for (int b = h * (NBLK / 16); b < (h + 1) * (NBLK / 16); ++b) {
            si += g_part_imp[b][e];
            sp += g_part_p[b][e];
        }
        float* sa = sm;          // reuse smem (post-sync); [16][64]
        float* sb = sm + 1024;
        __syncthreads();
        sa[h * 64 + e] = si;
        sb[h * 64 + e] = sp;
        __syncthreads();
        if (tid == 0) {
            float ma = 0.f, mp = 0.f;
            float va = 0.f, vp = 0.f;
            float ia[NEXP], pa[NEXP];
            for (int i = 0; i < NEXP; i++) {
                float s1 = 0.f, s2 = 0.f;
                for (int hh = 0; hh < 16; hh++) {
                    s1 += sa[hh * 64 + i];
                    s2 += sb[hh * 64 + i];
                }
                ia[i] = s1;
                pa[i] = s2 * (1.0f / NTOK);
                ma += ia[i];
                mp += pa[i];
            }
            ma *= (1.0f / NEXP);
            mp *= (1.0f / NEXP);
            for (int i = 0; i < NEXP; i++) {
                const float da = ia[i] - ma;
                const float dp = pa[i] - mp;
                va += da * da;
                vp += dp * dp;
            }
            va *= (1.0f / (NEXP - 1));  // ddof=1
            vp *= (1.0f / (NEXP - 1));
            const float il = va / ((ma + 1e-8f) * (ma + 1e-8f));
            const float ll = vp / ((mp + 1e-8f) * (mp + 1e-8f));
            g_ctr = 0;  // reset for next graph replay
            out[4 * NTOK] = 0.5f * (il + ll);
        }
    }
}

extern "C" void kernel_launch(void* const* d_in, const int* in_sizes, int n_in,
                              void* d_out, int out_size) {
    const float* x     = (const float*)d_in[0];
    const float* W     = (const float*)d_in[1];
    const float* b     = (const float*)d_in[2];
    const float* noise = (const float*)d_in[3];
    float* out = (float*)d_out;

    cudaFuncSetAttribute(router_main, cudaFuncAttributeMaxDynamicSharedMemorySize, SMEM_BYTES);
    wconv<<<256, 256>>>(W);
    router_main<<<NBLK, NTHR, SMEM_BYTES>>>(x, b, noise, out);
}

// round 16
// speedup vs baseline: 1.2754x; 1.2754x over previous
#include <cuda_runtime.h>
#include <cuda_pipeline.h>
#include <math.h>
#include <stdint.h>

#define NTOK 16384
#define DDIM 2048
#define NEXP 64
#define TM   128
#define NBLK (NTOK / TM)      // 128 blocks
#define NTHR 1024             // 32 warps, 8 per SMSP
#define KC   64
#define NCHUNK (DDIM / KC)    // 32 chunks
#define APITCH 72             // A smem pitch (floats): conflict-free LDS.64 frags
#define ASZ (TM * APITCH)     // 9216 f per buffer
#define BPITCH 72             // packed-B pitch (u32): conflict-free scalar LDS
#define BSZ (32 * BPITCH)     // 2304 u32 per buffer per array
#define NOISE_STD (1.0f / 64.0f)

// smem float offsets (double-buffered, depth 2) — identical to R13 best
#define OFF_ARAW 0                       // 2 x 9216 = 18432
#define OFF_BH   (2 * ASZ)               // 2 x 2304 = 4608
#define OFF_BL   (OFF_BH + 2 * BSZ)      // 2 x 2304
#define SMEM_F   (OFF_BL + 2 * BSZ)      // 27648 floats
#define SMEM_BYTES (SMEM_F * 4)          // 110592 B -> 1 CTA/SM

// device scratch (no cudaMalloc allowed)
__device__ float    g_part_imp[NBLK][NEXP];
__device__ float    g_part_p[NBLK][NEXP];
// packed W bf16x2: g_wbh[k2*64+n] = {lo: bf16(W[2k2][n]), hi: bf16(W[2k2+1][n])}
__device__ uint32_t g_wbh[(DDIM / 2) * NEXP];
__device__ uint32_t g_wbl[(DDIM / 2) * NEXP];
__device__ int      g_ctr;

// pack two fp32 -> bf16x2 (RN): lower half = e0, upper half = e1
__device__ __forceinline__ uint32_t pack_bf16x2(float e0, float e1) {
    uint32_t r;
    asm("cvt.rn.satfinite.bf16x2.f32 %0, %1, %2;" : "=r"(r) : "f"(e1), "f"(e0));
    return r;
}
__device__ __forceinline__ void mma_bf16(float* c, const uint32_t* a,
                                         uint32_t b0, uint32_t b1) {
    asm volatile(
        "mma.sync.aligned.m16n8k16.row.col.f32.bf16.bf16.f32 "
        "{%0,%1,%2,%3}, {%4,%5,%6,%7}, {%8,%9}, {%0,%1,%2,%3};"
        : "+f"(c[0]), "+f"(c[1]), "+f"(c[2]), "+f"(c[3])
        : "r"(a[0]), "r"(a[1]), "r"(a[2]), "r"(a[3]), "r"(b0), "r"(b1));
}
// split a float2 (consecutive k) into bf16x2 hi and lo parts
__device__ __forceinline__ void split_pair(float2 p, uint32_t& hi2, uint32_t& lo2) {
    hi2 = pack_bf16x2(p.x, p.y);
    const float h0 = __uint_as_float(hi2 << 16);
    const float h1 = __uint_as_float(hi2 & 0xFFFF0000u);
    lo2 = pack_bf16x2(p.x - h0, p.y - h1);
}
__device__ __forceinline__ bool gtv(float a, int ia, float b, int ib) {
    return (a > b) || (a == b && ia < ib);
}

// ---- prologue: split W into packed bf16x2 hi/lo pairs (k-pairs in one u32)
__global__ void __launch_bounds__(256) wconv(const float* __restrict__ W) {
    const int idx = blockIdx.x * 256 + threadIdx.x;   // 256 blocks -> 65536
    const int k2 = idx >> 6, n = idx & 63;
    const float f0 = W[(size_t)(2 * k2) * NEXP + n];
    const float f1 = W[(size_t)(2 * k2 + 1) * NEXP + n];
    uint32_t h2, l2;
    split_pair(make_float2(f0, f1), h2, l2);
    g_wbh[k2 * 64 + n] = h2;
    g_wbl[k2 * 64 + n] = l2;
}

__global__ void __launch_bounds__(NTHR)
router_main(const float* __restrict__ x, const float* __restrict__ bias_g,
            const float* __restrict__ noise, float* __restrict__ out) {
    extern __shared__ __align__(16) float sm[];

    const int tid  = threadIdx.x;
    const int lane = tid & 31;
    const int w    = tid >> 5;    // warp 0..31
    const int kset = w >> 4;      // 0: k-steps 0-1, 1: k-steps 2-3 of each chunk
    const int w16  = w & 15;
    const int mg   = w16 & 7;     // m-tile: rows [mg*16, mg*16+16)
    const int nb   = (w16 >> 3) * 32;  // n base 0 or 32; warp covers 4 n-tiles
    const int g    = lane >> 2;   // 0..7
    const int l4   = lane & 3;    // 0..3
    const int bm   = blockIdx.x * TM;

    // staging A: 8 threads per token row, 8 consecutive floats each
    const int tokS = tid >> 3;         // 0..127
    const int qS   = (tid & 7) * 8;    // 0..56
    const float* xsrc = x + (size_t)(bm + tokS) * DDIM + qS;
    // staging B: thread copies 2 u32 of packed row kB2 (both hi and lo arrays)
    const int kB2 = tid >> 5;          // 0..31
    const int qB  = lane * 2;          // 0..62

    uint32_t* Bh_base = (uint32_t*)(sm + OFF_BH);
    uint32_t* Bl_base = (uint32_t*)(sm + OFF_BL);

    auto stage = [&](int c) {
        if (c < NCHUNK) {
            float* ad = sm + OFF_ARAW + (c & 1) * ASZ + tokS * APITCH + qS;
            const float* as = xsrc + c * KC;
            __pipeline_memcpy_async(ad, as, 16);
            __pipeline_memcpy_async(ad + 4, as + 4, 16);
            const int bsrc = c * (KC / 2) * 64 + kB2 * 64 + qB;
            const int bdst = kB2 * BPITCH + qB;
            __pipeline_memcpy_async(Bh_base + (c & 1) * BSZ + bdst, g_wbh + bsrc, 8);
            __pipeline_memcpy_async(Bl_base + (c & 1) * BSZ + bdst, g_wbl + bsrc, 8);
        }
        __pipeline_commit();
    };

    float acc[4][4];
#pragma unroll
    for (int ni = 0; ni < 4; ni++)
#pragma unroll
        for (int r = 0; r < 4; r++) acc[ni][r] = 0.f;

    stage(0); stage(1);
    __pipeline_wait_prior(1);   // chunk 0 landed (thread-local)
    __syncthreads();            // chunk 0 visible block-wide

    const int r0 = mg * 16 + g;

    for (int c = 0; c < NCHUNK; ++c) {
        // invariant: chunk c visible block-wide; chunk c+1 in flight
        const float* Ar = sm + OFF_ARAW + (c & 1) * ASZ;
        const uint32_t* Bh = Bh_base + (c & 1) * BSZ;
        const uint32_t* Bl = Bl_base + (c & 1) * BSZ;

#pragma unroll
        for (int kh = 0; kh < 2; kh++) {            // this kset's 2 k16 steps
            const int ks = kset * 2 + kh;
            const int k0 = ks * 16 + 2 * l4;
            // A fragment: 4x LDS.64 of consecutive k-pairs, bf16 split in regs
            const float2 p0 = *(const float2*)(Ar + r0 * APITCH + k0);
            const float2 p1 = *(const float2*)(Ar + (r0 + 8) * APITCH + k0);
            const float2 p2 = *(const float2*)(Ar + r0 * APITCH + k0 + 8);
            const float2 p3 = *(const float2*)(Ar + (r0 + 8) * APITCH + k0 + 8);
            uint32_t ah[4], al[4];
            split_pair(p0, ah[0], al[0]);
            split_pair(p1, ah[1], al[1]);
            split_pair(p2, ah[2], al[2]);
            split_pair(p3, ah[3], al[3]);
            // B fragments: rows k2 = ks*8 + l4 (+4); 4 n-tiles
            const int kr = ks * 8 + l4;
#pragma unroll
            for (int ni = 0; ni < 4; ni++) {
                const int n = nb + ni * 8 + g;
                const uint32_t bh0 = Bh[kr * BPITCH + n];
                const uint32_t bh1 = Bh[(kr + 4) * BPITCH + n];
                const uint32_t bl0 = Bl[kr * BPITCH + n];
                const uint32_t bl1 = Bl[(kr + 4) * BPITCH + n];
                mma_bf16(acc[ni], ah, bh0, bh1);   // hh
                mma_bf16(acc[ni], ah, bl0, bl1);   // hl
                mma_bf16(acc[ni], al, bh0, bh1);   // lh
            }
        }

        __syncthreads();           // all reads of buf (c&1) complete block-wide
        stage(c + 2);              // overwrite buf (c&1) (async)
        __pipeline_wait_prior(1);  // chunk c+1 landed (thread-local)
        __syncthreads();           // cross-thread: chunk c+1 visible
    }

    // ---- combine K-split partials into Ls[128][66] (reuses ARAW; loop ended w/ sync)
    float* Ls = sm;
    if (kset == 0) {
#pragma unroll
        for (int ni = 0; ni < 4; ni++) {
            const int row = mg * 16 + g;
            const int col = nb + ni * 8 + l4 * 2;
            *(float2*)(Ls + row * 66 + col) = make_float2(acc[ni][0], acc[ni][1]);
            *(float2*)(Ls + (row + 8) * 66 + col) = make_float2(acc[ni][2], acc[ni][3]);
        }
    }
    __syncthreads();
    if (kset == 1) {
#pragma unroll
        for (int ni = 0; ni < 4; ni++) {
            const int row = mg * 16 + g;
            const int col = nb + ni * 8 + l4 * 2;
            float2 a0 = *(const float2*)(Ls + row * 66 + col);
            float2 a1 = *(const float2*)(Ls + (row + 8) * 66 + col);
            a0.x += acc[ni][0]; a0.y += acc[ni][1];
            a1.x += acc[ni][2]; a1.y += acc[ni][3];
            *(float2*)(Ls + row * 66 + col) = a0;
            *(float2*)(Ls + (row + 8) * 66 + col) = a1;
        }
    }
    __syncthreads();

    // ---- per-token epilogue: warp w handles tokens [w*4, w*4+4)
    const int e0 = 2 * lane;
    const int e1 = 2 * lane + 1;
    const float bb0 = __ldg(bias_g + e0);
    const float bb1 = __ldg(bias_g + e1);

    float imp0 = 0.f, imp1 = 0.f, pa0 = 0.f, pa1 = 0.f;

    for (int tt = 0; tt < 4; ++tt) {
        const int tl = w * 4 + tt;
        const int t  = bm + tl;
        const float2 L2 = *(const float2*)(Ls + tl * 66 + e0);
        const float l0 = L2.x + bb0, l1 = L2.y + bb1;

        float mx = fmaxf(l0, l1);
#pragma unroll
        for (int off = 16; off; off >>= 1)
            mx = fmaxf(mx, __shfl_xor_sync(0xffffffffu, mx, off));
        const float s0 = __expf(l0 - mx);
        const float s1 = __expf(l1 - mx);
        float ss = s0 + s1;
#pragma unroll
        for (int off = 16; off; off >>= 1)
            ss += __shfl_xor_sync(0xffffffffu, ss, off);
        const float rs = 1.0f / ss;
        imp0 += s0 * rs;
        imp1 += s1 * rs;

        const float2 nz = *(const float2*)(noise + (size_t)t * NEXP + e0);
        const float n0 = fmaf(NOISE_STD, nz.x, l0);
        const float n1 = fmaf(NOISE_STD, nz.y, l1);
        float v1, v2;
        int i1, i2;
        if (n0 >= n1) { v1 = n0; i1 = e0; v2 = n1; i2 = e1; }
        else          { v1 = n1; i1 = e1; v2 = n0; i2 = e0; }
#pragma unroll
        for (int off = 16; off; off >>= 1) {
            const float ov1 = __shfl_xor_sync(0xffffffffu, v1, off);
            const int   oi1 = __shfl_xor_sync(0xffffffffu, i1, off);
            const float ov2 = __shfl_xor_sync(0xffffffffu, v2, off);
            const int   oi2 = __shfl_xor_sync(0xffffffffu, i2, off);
            if (gtv(ov1, oi1, v1, i1)) {
                if (gtv(v1, i1, ov2, oi2)) { v2 = v1; i2 = i1; }
                else                       { v2 = ov2; i2 = oi2; }
                v1 = ov1; i1 = oi1;
            } else if (gtv(ov1, oi1, v2, i2)) {
                v2 = ov1; i2 = oi1;
            }
        }

        const float ee = __expf(v2 - v1);
        const float g1 = 1.0f / (1.0f + ee);
        const float g2 = ee * g1;

        const float z0 = (v2 - l0) * 64.0f;
        const float z1 = (v2 - l1) * 64.0f;
        pa0 += normcdff(-z0);
        pa1 += normcdff(-z1);

        if (lane == 0) {
            out[2 * t + 0] = g1;
            out[2 * t + 1] = g2;
            out[2 * NTOK + 2 * t + 0] = (float)i1;
            out[2 * NTOK + 2 * t + 1] = (float)i2;
        }
    }

    // ---- block partials (deterministic layout; 32 warps)
    float* redI = sm + 8448;          // [32][64]
    float* redP = sm + 8448 + 2048;   // [32][64]
    redI[w * 64 + e0] = imp0;
    redI[w * 64 + e1] = imp1;
    redP[w * 64 + e0] = pa0;
    redP[w * 64 + e1] = pa1;
    __syncthreads();
    if (tid < NEXP) {
        float si = 0.f, sp = 0.f;
#pragma unroll
        for (int r = 0; r < 32; r++) {
            si += redI[r * 64 + tid];
            sp += redP[r * 64 + tid];
        }
        g_part_imp[blockIdx.x][tid] = si;
        g_part_p[blockIdx.x][tid]   = sp;
    }

    // ---- last CTA computes aux loss (fixed-order sums -> deterministic)
    __threadfence();
    __shared__ int s_ticket;
    if (tid == 0) s_ticket = atomicAdd(&g_ctr, 1);
    __syncthreads();
    if (s_ticket == NBLK - 1) {
        const int e = tid & 63;
        const int h = tid >> 6;  // 0..15
        float si = 0.f, sp = 0.f;
        for (int b = h * (NBLK / 16); b < (h + 1) * (NBLK / 16); ++b) {
            si += g_part_imp[b][e];
            sp += g_part_p[b][e];
        }
        float* sa = sm;          // reuse smem (post-sync); [16][64]
        float* sb = sm + 1024;
        __syncthreads();
        sa[h * 64 + e] = si;
        sb[h * 64 + e] = sp;
        __syncthreads();
        if (tid == 0) {
            float ma = 0.f, mp = 0.f;
            float va = 0.f, vp = 0.f;
            float ia[NEXP], pa[NEXP];
            for (int i = 0; i < NEXP; i++) {
                float s1 = 0.f, s2 = 0.f;
                for (int hh = 0; hh < 16; hh++) {
                    s1 += sa[hh * 64 + i];
                    s2 += sb[hh * 64 + i];
                }
                ia[i] = s1;
                pa[i] = s2 * (1.0f / NTOK);
                ma += ia[i];
                mp += pa[i];
            }
            ma *= (1.0f / NEXP);
            mp *= (1.0f / NEXP);
            for (int i = 0; i < NEXP; i++) {
                const float da = ia[i] - ma;
                const float dp = pa[i] - mp;
                va += da * da;
                vp += dp * dp;
            }
            va *= (1.0f / (NEXP - 1));  // ddof=1
            vp *= (1.0f / (NEXP - 1));
            const float il = va / ((ma + 1e-8f) * (ma + 1e-8f));
            const float ll = vp / ((mp + 1e-8f) * (mp + 1e-8f));
            g_ctr = 0;  // reset for next graph replay
            out[4 * NTOK] = 0.5f * (il + ll);
        }
    }
}

extern "C" void kernel_launch(void* const* d_in, const int* in_sizes, int n_in,
                              void* d_out, int out_size) {
    const float* x     = (const float*)d_in[0];
    const float* W     = (const float*)d_in[1];
    const float* b     = (const float*)d_in[2];
    const float* noise = (const float*)d_in[3];
    float* out = (float*)d_out;

    cudaFuncSetAttribute(router_main, cudaFuncAttributeMaxDynamicSharedMemorySize, SMEM_BYTES);
    wconv<<<256, 256>>>(W);
    router_main<<<NBLK, NTHR, SMEM_BYTES>>>(x, b, noise, out);
}